// round 11
// baseline (speedup 1.0000x reference)
#include <cuda_runtime.h>
#include <math.h>

__device__ double g_sum = 0.0;

#define FULLM 0xFFFFFFFFu
#define BW 256
#define SPAN9 (9 * (BW + 1))   // 2313 floats: 257 face/vertex rows
#define SPAN9B (9 * BW)        // 2304 floats: 256 rows

struct V3 { float x, y, z; };

__device__ __forceinline__ V3 ld3(const float* __restrict__ p) { return {p[0], p[1], p[2]}; }
__device__ __forceinline__ V3 vsub(V3 a, V3 b) { return {a.x - b.x, a.y - b.y, a.z - b.z}; }
__device__ __forceinline__ float vdot(V3 a, V3 b) { return a.x * b.x + a.y * b.y + a.z * b.z; }
__device__ __forceinline__ V3 vcross(V3 a, V3 b) {
    return {a.y * b.z - a.z * b.y,
            a.z * b.x - a.x * b.z,
            a.x * b.y - a.y * b.x};
}
__device__ __forceinline__ V3 face_normal_s(const float* q) {   // smem source
    V3 t0 = ld3(q), t1 = ld3(q + 3), t2 = ld3(q + 6);
    V3 c = vcross(vsub(t0, t1), vsub(t0, t2));
    float s = rsqrtf(vdot(c, c));
    return {c.x * s, c.y * s, c.z * s};
}
__device__ __forceinline__ float tri_area(V3 p1, V3 p2, V3 p3) {
    V3 c = vcross(vsub(p2, p1), vsub(p3, p1));
    return 0.5f * sqrtf(vdot(c, c));
}

// Closed form of (pair*coeff).sum()/9 with x = na@(r1-r2), y = nb@(r1-r2).
__device__ __forceinline__ float edge_term(
    V3 u, V3 w, V3 na, V3 nb,
    const float* r1, const float* r2,
    float dv2, float asum)
{
    V3 x = {0, 0, 0}, y = {0, 0, 0};
    #pragma unroll
    for (int c = 0; c < 3; c++) {
        float d0 = r1[3 * c + 0] - r2[3 * c + 0];
        float d1 = r1[3 * c + 1] - r2[3 * c + 1];
        float d2 = r1[3 * c + 2] - r2[3 * c + 2];
        float ac = (c == 0) ? na.x : ((c == 1) ? na.y : na.z);
        float bc = (c == 0) ? nb.x : ((c == 1) ? nb.y : nb.z);
        x.x += ac * d0; x.y += ac * d1; x.z += ac * d2;
        y.x += bc * d0; y.y += bc * d1; y.z += bc * d2;
    }
    float en = (3.0f * (vdot(u, u) + vdot(w, w) + vdot(u, w))
              + vdot(x, x) + vdot(y, y) + vdot(x, y)) * (1.0f / 9.0f);
    return en * (dv2 / asum);
}

// One thread per grid cell (i,j); up to 3 interior edges per cell (see R2-R8).
// tri1(i,j)=i*m+j, tri2(i,j)=m*m+i*m+j (m=n-1). Edge-endpoint "normals" come
// from tp[vertex_id] blocks (reference indexes normals by vertex ids).
// The 4 highest-wavefront spans (36B-stride, 9-float rows) are staged in smem
// with coalesced loads; stride-9 LDS reads are bank-conflict-free (gcd(9,32)=1).
// smem ~37KB/block; reg cap (256,5) already limits to 5 blocks/SM, so staging
// is occupancy-neutral (5*37KB=185KB < 228KB).
__global__ __launch_bounds__(BW, 5)
void k_cell(const float* __restrict__ tp,     // (F,3,3)
            const float* __restrict__ rot,    // (F,3,3)
            const float* __restrict__ verts,  // (V,3)
            int n)
{
    const int m   = n - 1;
    const int tid = threadIdx.x;
    const int j0  = blockIdx.x * BW;
    const int i   = blockIdx.y;
    const int j   = j0 + tid;

    __shared__ float sT1[SPAN9];   // tp rows [i*m+j0 .. +256]      (q1, qr)
    __shared__ float sR1[SPAN9];   // rot rows [i*m+j0 .. +256]     (r1, rR)
    __shared__ float sA [SPAN9];   // tp rows [(i+1)n+j0 .. +256]   (n10, n11)
    __shared__ float sB [SPAN9B];  // tp rows [i*n+j0+1 .. +256]    (n01)
    __shared__ double sred[8];

    const int limTP  = 2 * m * m * 9;
    const int baseT1 = 9 * (i * m + j0);
    const int baseA  = 9 * ((i + 1) * n + j0);
    const int baseB  = 9 * (i * n + j0 + 1);

    #pragma unroll 1
    for (int k = tid; k < SPAN9; k += BW) {
        int gT = min(baseT1 + k, limTP - 1);
        int gA = min(baseA  + k, limTP - 1);
        sT1[k] = tp[gT];
        sR1[k] = rot[gT];
        sA [k] = tp[gA];
    }
    #pragma unroll 1
    for (int k = tid; k < SPAN9B; k += BW) {
        int gB = min(baseB + k, limTP - 1);
        sB[k] = tp[gB];
    }
    __syncthreads();

    float val = 0.0f;
    if (j < m) {
        const int k = tid;
        int v00 = i * n + j;
        int v10 = v00 + n;
        int v01 = v00 + 1;
        int v11 = v10 + 1;
        int fT2 = m * m + i * m + j;

        V3 p00 = ld3(verts + 3 * (size_t)v00);
        V3 p10 = ld3(verts + 3 * (size_t)v10);
        V3 p01 = ld3(verts + 3 * (size_t)v01);
        V3 p11 = ld3(verts + 3 * (size_t)v11);

        float aT1 = tri_area(p00, p10, p01);
        float aT2 = tri_area(p10, p11, p01);

        // staged spans
        const float* q1 = sT1 + 9 * k;
        const float* qr = sT1 + 9 * (k + 1);
        const float* r1 = sR1 + 9 * k;
        const float* rR = sR1 + 9 * (k + 1);
        V3 n10 = face_normal_s(sA + 9 * k);
        V3 n11 = face_normal_s(sA + 9 * (k + 1));
        V3 n01 = face_normal_s(sB + 9 * k);

        V3 t1_1 = ld3(q1 + 3), t1_2 = ld3(q1 + 6);

        // direct global (lower-traffic fields)
        const float* q2 = tp  + 9 * (size_t)fT2;
        const float* r2 = rot + 9 * (size_t)fT2;
        V3 t2_0 = ld3(q2), t2_1 = ld3(q2 + 3), t2_2 = ld3(q2 + 6);

        // diagonal edge (v10, v01)
        {
            V3 u = vsub(t1_1, t2_0), w = vsub(t1_2, t2_2), d = vsub(p10, p01);
            val += edge_term(u, w, n10, n01, r1, r2, vdot(d, d), aT1 + aT2);
        }
        // horizontal edge (v10, v11) vs tri1(i+1, j)
        if (i < m - 1) {
            int fD = i * m + j + m;
            const float* qd = tp + 9 * (size_t)fD;
            V3 td_0 = ld3(qd), td_2 = ld3(qd + 6);
            V3 p20 = ld3(verts + 3 * (size_t)(v10 + n));
            float aD = tri_area(p10, p20, p11);
            V3 u = vsub(t2_0, td_0), w = vsub(t2_1, td_2), d = vsub(p10, p11);
            val += edge_term(u, w, n10, n11, r2, rot + 9 * (size_t)fD, vdot(d, d), aT2 + aD);
        }
        // vertical edge (v11, v01) vs tri1(i, j+1)
        if (j < m - 1) {
            V3 tr_0 = ld3(qr), tr_1 = ld3(qr + 3);
            V3 p02 = ld3(verts + 3 * (size_t)(v01 + 1));
            float aR = tri_area(p01, p11, p02);
            V3 u = vsub(t2_1, tr_1), w = vsub(t2_2, tr_0), d = vsub(p11, p01);
            val += edge_term(u, w, n11, n01, r2, rR, vdot(d, d), aT2 + aR);
        }
    }

    // ---- warp reduce (fp32) -> cross-warp (fp64) -> one atomic per block ----
    #pragma unroll
    for (int off = 16; off > 0; off >>= 1)
        val += __shfl_down_sync(FULLM, val, off);

    int lane = tid & 31, wid = tid >> 5;
    if (lane == 0) sred[wid] = (double)val;
    __syncthreads();
    if (tid == 0) {
        double bsum = 0.0;
        #pragma unroll
        for (int w = 0; w < 8; w++) bsum += sred[w];
        atomicAdd(&g_sum, bsum);
    }
}

// Write result and reset accumulator for the next graph replay.
__global__ void k_fin(float* __restrict__ out) {
    out[0] = (float)g_sum;
    g_sum = 0.0;
}

extern "C" void kernel_launch(void* const* d_in, const int* in_sizes, int n_in,
                              void* d_out, int out_size)
{
    const float* tp    = (const float*)d_in[0];   // (F,3,3)
    const float* rot   = (const float*)d_in[1];   // (F,3,3)
    const float* verts = (const float*)d_in[2];   // (1,V,3)

    int V = in_sizes[2] / 3;
    int n = (int)(sqrt((double)V) + 0.5);
    int m = n - 1;

    dim3 block(BW, 1, 1);
    dim3 grid((m + BW - 1) / BW, m, 1);

    k_cell<<<grid, block>>>(tp, rot, verts, n);
    k_fin<<<1, 1>>>((float*)d_out);
}

// round 12
// speedup vs baseline: 1.5953x; 1.5953x over previous
#include <cuda_runtime.h>
#include <math.h>

__device__ double g_sum = 0.0;

#define FULLM 0xFFFFFFFFu

struct V3 { float x, y, z; };

__device__ __forceinline__ V3 ld3(const float* __restrict__ p) { return {p[0], p[1], p[2]}; }
__device__ __forceinline__ V3 vsub(V3 a, V3 b) { return {a.x - b.x, a.y - b.y, a.z - b.z}; }
__device__ __forceinline__ float vdot(V3 a, V3 b) { return a.x * b.x + a.y * b.y + a.z * b.z; }
__device__ __forceinline__ V3 vcross(V3 a, V3 b) {
    return {a.y * b.z - a.z * b.y,
            a.z * b.x - a.x * b.z,
            a.x * b.y - a.y * b.x};
}
__device__ __forceinline__ V3 face_normal(const float* __restrict__ q) {
    V3 t0 = ld3(q), t1 = ld3(q + 3), t2 = ld3(q + 6);
    V3 c = vcross(vsub(t0, t1), vsub(t0, t2));
    float s = rsqrtf(vdot(c, c));
    return {c.x * s, c.y * s, c.z * s};
}
__device__ __forceinline__ float tri_area(V3 p1, V3 p2, V3 p3) {
    V3 c = vcross(vsub(p2, p1), vsub(p3, p1));
    return 0.5f * sqrtf(vdot(c, c));
}

// Closed form of (pair*coeff).sum()/9 with x = na@(r1-r2), y = nb@(r1-r2).
__device__ __forceinline__ float edge_term(
    V3 u, V3 w, V3 na, V3 nb,
    const float* __restrict__ r1, const float* __restrict__ r2,
    float dv2, float asum)
{
    V3 x = {0, 0, 0}, y = {0, 0, 0};
    #pragma unroll
    for (int c = 0; c < 3; c++) {
        float d0 = r1[3 * c + 0] - r2[3 * c + 0];
        float d1 = r1[3 * c + 1] - r2[3 * c + 1];
        float d2 = r1[3 * c + 2] - r2[3 * c + 2];
        float ac = (c == 0) ? na.x : ((c == 1) ? na.y : na.z);
        float bc = (c == 0) ? nb.x : ((c == 1) ? nb.y : nb.z);
        x.x += ac * d0; x.y += ac * d1; x.z += ac * d2;
        y.x += bc * d0; y.y += bc * d1; y.z += bc * d2;
    }
    float en = (3.0f * (vdot(u, u) + vdot(w, w) + vdot(u, w))
              + vdot(x, x) + vdot(y, y) + vdot(x, y)) * (1.0f / 9.0f);
    return en * (dv2 / asum);
}

// TWO vertically-stacked cells per thread: A=(i0,j), B=(i0+1,j), i0=2*blockIdx.y.
// Shared between A and B (kept in registers): rot[tri1(i0+1,j)] (A.rD == B.r1),
// normal of vertex (i0+1)n+j+1 (A.n11 == B.n01), area tri1(i0+1,j) (A.aD ==
// B.aT1), verts rows i0+1/i0+2, tp[tri1(i0+1,j)] row 2.
// Per cell, up to 3 interior edges (diag always; horiz if i<m-1; vert if j<m-1).
// tri1(i,j)=i*m+j, tri2(i,j)=m*m+i*m+j (m=n-1). "Normals" come from
// tp[vertex_id] (reference indexes normals by vertex ids).
__global__ __launch_bounds__(256, 4)
void k_cell(const float* __restrict__ tp,     // (F,3,3)
            const float* __restrict__ rot,    // (F,3,3)
            const float* __restrict__ verts,  // (V,3)
            int n)
{
    const int m  = n - 1;
    const int j  = blockIdx.x * blockDim.x + threadIdx.x;
    const int i0 = blockIdx.y * 2;
    float val = 0.0f;

    if (j < m) {
        const bool vertE = (j < m - 1);
        const bool hasB  = (i0 < m - 1);       // == A's horizontal-edge condition

        // ---------------- cell A = (i0, j) ----------------
        const int vA00 = i0 * n + j;           // row i0
        const int vA10 = vA00 + n;             // row i0+1
        const int fA1  = i0 * m + j;           // tri1(i0,j)
        const int fA2  = m * m + fA1;          // tri2(i0,j)

        V3 a00 = ld3(verts + 3 * (size_t)vA00);
        V3 a01 = ld3(verts + 3 * (size_t)(vA00 + 1));
        V3 b00 = ld3(verts + 3 * (size_t)vA10);
        V3 b01 = ld3(verts + 3 * (size_t)(vA10 + 1));

        float aT1A = tri_area(a00, b00, a01);
        float aT2A = tri_area(b00, b01, a01);

        const float* q1 = tp + 9 * (size_t)fA1;
        const float* q2 = tp + 9 * (size_t)fA2;
        V3 tA1_1 = ld3(q1 + 3), tA1_2 = ld3(q1 + 6);
        V3 tA2_0 = ld3(q2), tA2_1 = ld3(q2 + 3), tA2_2 = ld3(q2 + 6);

        V3 nA10 = face_normal(tp + 9 * (size_t)vA10);        // vertex (i0+1)n+j
        V3 nA01 = face_normal(tp + 9 * (size_t)(vA00 + 1));  // vertex i0*n+j+1
        V3 nA11 = face_normal(tp + 9 * (size_t)(vA10 + 1));  // vertex (i0+1)n+j+1

        const float* r1A = rot + 9 * (size_t)fA1;
        const float* r2A = rot + 9 * (size_t)fA2;

        // A: diagonal edge (v10, v01)
        {
            V3 u = vsub(tA1_1, tA2_0), w = vsub(tA1_2, tA2_2), d = vsub(b00, a01);
            val += edge_term(u, w, nA10, nA01, r1A, r2A, vdot(d, d), aT1A + aT2A);
        }
        // A: vertical edge (v11, v01) vs tri1(i0, j+1)
        if (vertE) {
            const float* qr = tp + 9 * (size_t)(fA1 + 1);
            V3 tr_0 = ld3(qr), tr_1 = ld3(qr + 3);
            V3 a02 = ld3(verts + 3 * (size_t)(vA00 + 2));
            float aRA = tri_area(a01, b01, a02);
            V3 u = vsub(tA2_1, tr_1), w = vsub(tA2_2, tr_0), d = vsub(b01, a01);
            val += edge_term(u, w, nA11, nA01, r2A, rot + 9 * (size_t)(fA1 + 1),
                             vdot(d, d), aT2A + aRA);
        }

        // ------- shared section: A's horizontal edge + all of cell B -------
        if (hasB) {
            const int fB1 = fA1 + m;             // tri1(i0+1,j) == A's fD
            const int fB2 = m * m + fB1;
            const int vB10 = vA10 + n;           // row i0+2

            // shared loads
            V3 c00 = ld3(verts + 3 * (size_t)vB10);
            V3 c01 = ld3(verts + 3 * (size_t)(vB10 + 1));
            const float* qB1 = tp + 9 * (size_t)fB1;
            V3 tB1_0 = ld3(qB1), tB1_1 = ld3(qB1 + 3), tB1_2 = ld3(qB1 + 6);
            const float* rB1 = rot + 9 * (size_t)fB1;   // == A's rD

            float aT1B = tri_area(b00, c00, b01);        // == A's aD

            // A: horizontal edge (v10, v11) vs tri1(i0+1, j)
            {
                V3 u = vsub(tA2_0, tB1_0), w = vsub(tA2_1, tB1_2), d = vsub(b00, b01);
                val += edge_term(u, w, nA10, nA11, r2A, rB1, vdot(d, d), aT2A + aT1B);
            }

            // ---------------- cell B = (i0+1, j) ----------------
            const float* qB2 = tp + 9 * (size_t)fB2;
            V3 tB2_0 = ld3(qB2), tB2_1 = ld3(qB2 + 3), tB2_2 = ld3(qB2 + 6);

            V3 nB10 = face_normal(tp + 9 * (size_t)vB10);        // vertex (i0+2)n+j
            V3 nB11 = face_normal(tp + 9 * (size_t)(vB10 + 1));  // vertex (i0+2)n+j+1
            // nB01 == nA11 (vertex (i0+1)n+j+1) -- reuse, no load

            const float* r2B = rot + 9 * (size_t)fB2;
            float aT2B = tri_area(c00, c01, b01);

            // B: diagonal edge (v10, v01)
            {
                V3 u = vsub(tB1_1, tB2_0), w = vsub(tB1_2, tB2_2), d = vsub(c00, b01);
                val += edge_term(u, w, nB10, nA11, rB1, r2B, vdot(d, d), aT1B + aT2B);
            }
            // B: horizontal edge (v10, v11) vs tri1(i0+2, j)
            if (i0 + 1 < m - 1) {
                const int fBD = fB1 + m;
                const float* qd = tp + 9 * (size_t)fBD;
                V3 td_0 = ld3(qd), td_2 = ld3(qd + 6);
                V3 d00 = ld3(verts + 3 * (size_t)(vB10 + n));
                float aDB = tri_area(c00, d00, c01);
                V3 u = vsub(tB2_0, td_0), w = vsub(tB2_1, td_2), d = vsub(c00, c01);
                val += edge_term(u, w, nB10, nB11, r2B, rot + 9 * (size_t)fBD,
                                 vdot(d, d), aT2B + aDB);
            }
            // B: vertical edge (v11, v01) vs tri1(i0+1, j+1)
            if (vertE) {
                const float* qr = tp + 9 * (size_t)(fB1 + 1);
                V3 tr_0 = ld3(qr), tr_1 = ld3(qr + 3);
                V3 b02 = ld3(verts + 3 * (size_t)(vA10 + 2));
                float aRB = tri_area(b01, c01, b02);
                V3 u = vsub(tB2_1, tr_1), w = vsub(tB2_2, tr_0), d = vsub(c01, b01);
                val += edge_term(u, w, nB11, nA11, r2B, rot + 9 * (size_t)(fB1 + 1),
                                 vdot(d, d), aT2B + aRB);
            }
        }
    }

    // ---- warp reduce (fp32) -> cross-warp (fp64) -> one atomic per block ----
    #pragma unroll
    for (int off = 16; off > 0; off >>= 1)
        val += __shfl_down_sync(FULLM, val, off);

    __shared__ double sh[8];
    int lane = threadIdx.x & 31;
    int wid  = threadIdx.x >> 5;
    if (lane == 0) sh[wid] = (double)val;
    __syncthreads();
    if (threadIdx.x == 0) {
        double bsum = 0.0;
        #pragma unroll
        for (int w = 0; w < 8; w++) bsum += sh[w];
        atomicAdd(&g_sum, bsum);
    }
}

// Write result and reset accumulator for the next graph replay.
__global__ void k_fin(float* __restrict__ out) {
    out[0] = (float)g_sum;
    g_sum = 0.0;
}

extern "C" void kernel_launch(void* const* d_in, const int* in_sizes, int n_in,
                              void* d_out, int out_size)
{
    const float* tp    = (const float*)d_in[0];   // (F,3,3)
    const float* rot   = (const float*)d_in[1];   // (F,3,3)
    const float* verts = (const float*)d_in[2];   // (1,V,3)

    int V = in_sizes[2] / 3;
    int n = (int)(sqrt((double)V) + 0.5);
    int m = n - 1;

    dim3 block(256, 1, 1);
    dim3 grid((m + 255) / 256, (m + 1) / 2, 1);

    k_cell<<<grid, block>>>(tp, rot, verts, n);
    k_fin<<<1, 1>>>((float*)d_out);
}

// round 13
// speedup vs baseline: 1.6835x; 1.0553x over previous
#include <cuda_runtime.h>
#include <math.h>

__device__ double g_sum = 0.0;

#define FULLM 0xFFFFFFFFu
#define IC 4   // vertically-stacked cells per thread

struct V3 { float x, y, z; };

__device__ __forceinline__ V3 ld3(const float* __restrict__ p) { return {p[0], p[1], p[2]}; }
__device__ __forceinline__ V3 vsub(V3 a, V3 b) { return {a.x - b.x, a.y - b.y, a.z - b.z}; }
__device__ __forceinline__ float vdot(V3 a, V3 b) { return a.x * b.x + a.y * b.y + a.z * b.z; }
__device__ __forceinline__ V3 vcross(V3 a, V3 b) {
    return {a.y * b.z - a.z * b.y,
            a.z * b.x - a.x * b.z,
            a.x * b.y - a.y * b.x};
}
__device__ __forceinline__ V3 face_normal(const float* __restrict__ q) {
    V3 t0 = ld3(q), t1 = ld3(q + 3), t2 = ld3(q + 6);
    V3 c = vcross(vsub(t0, t1), vsub(t0, t2));
    float s = rsqrtf(vdot(c, c));
    return {c.x * s, c.y * s, c.z * s};
}
__device__ __forceinline__ float tri_area(V3 p1, V3 p2, V3 p3) {
    V3 c = vcross(vsub(p2, p1), vsub(p3, p1));
    return 0.5f * sqrtf(vdot(c, c));
}

// Closed form of (pair*coeff).sum()/9 with x = na@(r1-r2), y = nb@(r1-r2).
__device__ __forceinline__ float edge_term(
    V3 u, V3 w, V3 na, V3 nb,
    const float* __restrict__ r1, const float* __restrict__ r2,
    float dv2, float asum)
{
    V3 x = {0, 0, 0}, y = {0, 0, 0};
    #pragma unroll
    for (int c = 0; c < 3; c++) {
        float d0 = r1[3 * c + 0] - r2[3 * c + 0];
        float d1 = r1[3 * c + 1] - r2[3 * c + 1];
        float d2 = r1[3 * c + 2] - r2[3 * c + 2];
        float ac = (c == 0) ? na.x : ((c == 1) ? na.y : na.z);
        float bc = (c == 0) ? nb.x : ((c == 1) ? nb.y : nb.z);
        x.x += ac * d0; x.y += ac * d1; x.z += ac * d2;
        y.x += bc * d0; y.y += bc * d1; y.z += bc * d2;
    }
    float en = (3.0f * (vdot(u, u) + vdot(w, w) + vdot(u, w))
              + vdot(x, x) + vdot(y, y) + vdot(x, y)) * (1.0f / 9.0f);
    return en * (dv2 / asum);
}

// IC vertically-stacked cells per thread, rolling boundary state in registers:
// verts rows (pT<-pB<-pC), tp[tri1(i+1,j)] row (loaded for the horizontal edge,
// becomes next cell's t1), n11 -> next n01, aD -> next aT1.
// Per cell, up to 3 interior edges (diag always; horiz if i<m-1; vert if j<m-1).
// tri1(i,j)=i*m+j, tri2(i,j)=m*m+i*m+j (m=n-1). Edge-endpoint "normals" come
// from tp[vertex_id] (reference indexes normals by vertex ids).
__global__ __launch_bounds__(256, 4)
void k_cell(const float* __restrict__ tp,     // (F,3,3)
            const float* __restrict__ rot,    // (F,3,3)
            const float* __restrict__ verts,  // (V,3)
            int n)
{
    const int m  = n - 1;
    const int j  = blockIdx.x * blockDim.x + threadIdx.x;
    const int i0 = blockIdx.y * IC;
    float val = 0.0f;

    if (j < m) {
        const bool vertE = (j < m - 1);

        // ---- prologue: state for cell (i0, j) ----
        int i = i0;
        V3 pT0 = ld3(verts + 3 * (size_t)(i * n + j));
        V3 pT1 = ld3(verts + 3 * (size_t)(i * n + j + 1));
        V3 pB0 = ld3(verts + 3 * (size_t)((i + 1) * n + j));
        V3 pB1 = ld3(verts + 3 * (size_t)((i + 1) * n + j + 1));

        const float* q1 = tp + 9 * (size_t)(i * m + j);
        V3 t1_1 = ld3(q1 + 3), t1_2 = ld3(q1 + 6);   // t1_0 unused for first cell's edges
        V3 t1_0 = ld3(q1);                            // kept for symmetry of rolling

        V3 n10 = face_normal(tp + 9 * (size_t)((i + 1) * n + j));
        V3 n01 = face_normal(tp + 9 * (size_t)(i * n + j + 1));
        V3 n11 = face_normal(tp + 9 * (size_t)((i + 1) * n + j + 1));

        const float* r1 = rot + 9 * (size_t)(i * m + j);
        float aT1 = tri_area(pT0, pB0, pT1);

        #pragma unroll
        for (int s = 0; s < IC; s++, i++) {
            if (i >= m) break;

            const int fT2 = m * m + i * m + j;
            const float* q2 = tp  + 9 * (size_t)fT2;
            const float* r2 = rot + 9 * (size_t)fT2;
            V3 t2_0 = ld3(q2), t2_1 = ld3(q2 + 3), t2_2 = ld3(q2 + 6);

            float aT2 = tri_area(pB0, pB1, pT1);

            // diagonal edge (v10, v01)
            {
                V3 u = vsub(t1_1, t2_0), w = vsub(t1_2, t2_2), d = vsub(pB0, pT1);
                val += edge_term(u, w, n10, n01, r1, r2, vdot(d, d), aT1 + aT2);
            }
            // vertical edge (v11, v01) vs tri1(i, j+1)
            if (vertE) {
                const float* qr = tp + 9 * (size_t)(i * m + j + 1);
                V3 tr_0 = ld3(qr), tr_1 = ld3(qr + 3);
                V3 pT2 = ld3(verts + 3 * (size_t)(i * n + j + 2));
                float aR = tri_area(pT1, pB1, pT2);
                V3 u = vsub(t2_1, tr_1), w = vsub(t2_2, tr_0), d = vsub(pB1, pT1);
                val += edge_term(u, w, n11, n01, r2, rot + 9 * (size_t)(i * m + j + 1),
                                 vdot(d, d), aT2 + aR);
            }
            // horizontal edge (v10, v11) vs tri1(i+1, j)  [also rolls state]
            if (i < m - 1) {
                const int fD = (i + 1) * m + j;
                const float* qd = tp + 9 * (size_t)fD;
                V3 td_0 = ld3(qd), td_1 = ld3(qd + 3), td_2 = ld3(qd + 6);
                V3 pC0 = ld3(verts + 3 * (size_t)((i + 2) * n + j));
                V3 pC1 = ld3(verts + 3 * (size_t)((i + 2) * n + j + 1));
                float aD = tri_area(pB0, pC0, pB1);
                V3 u = vsub(t2_0, td_0), w = vsub(t2_1, td_2), d = vsub(pB0, pB1);
                val += edge_term(u, w, n10, n11, r2, rot + 9 * (size_t)fD,
                                 vdot(d, d), aT2 + aD);

                if (s + 1 < IC) {   // roll boundary state into next cell
                    pT0 = pB0; pT1 = pB1;
                    pB0 = pC0; pB1 = pC1;
                    t1_0 = td_0; t1_1 = td_1; t1_2 = td_2;
                    n01 = n11;
                    n10 = face_normal(tp + 9 * (size_t)((i + 2) * n + j));
                    n11 = face_normal(tp + 9 * (size_t)((i + 2) * n + j + 1));
                    r1  = rot + 9 * (size_t)fD;
                    aT1 = aD;
                }
            }
        }
    }

    // ---- warp reduce (fp32) -> cross-warp (fp64) -> one atomic per block ----
    #pragma unroll
    for (int off = 16; off > 0; off >>= 1)
        val += __shfl_down_sync(FULLM, val, off);

    __shared__ double sh[8];
    int lane = threadIdx.x & 31;
    int wid  = threadIdx.x >> 5;
    if (lane == 0) sh[wid] = (double)val;
    __syncthreads();
    if (threadIdx.x == 0) {
        double bsum = 0.0;
        #pragma unroll
        for (int w = 0; w < 8; w++) bsum += sh[w];
        atomicAdd(&g_sum, bsum);
    }
}

// Write result and reset accumulator for the next graph replay.
__global__ void k_fin(float* __restrict__ out) {
    out[0] = (float)g_sum;
    g_sum = 0.0;
}

extern "C" void kernel_launch(void* const* d_in, const int* in_sizes, int n_in,
                              void* d_out, int out_size)
{
    const float* tp    = (const float*)d_in[0];   // (F,3,3)
    const float* rot   = (const float*)d_in[1];   // (F,3,3)
    const float* verts = (const float*)d_in[2];   // (1,V,3)

    int V = in_sizes[2] / 3;
    int n = (int)(sqrt((double)V) + 0.5);
    int m = n - 1;

    dim3 block(256, 1, 1);
    dim3 grid((m + 255) / 256, (m + IC - 1) / IC, 1);

    k_cell<<<grid, block>>>(tp, rot, verts, n);
    k_fin<<<1, 1>>>((float*)d_out);
}